// round 15
// baseline (speedup 1.0000x reference)
#include <cuda_runtime.h>
#include <cuda_fp16.h>
#include <math.h>
#include <stdint.h>

#define E_DIM   768
#define S_DIM   1024
#define B_DIM   4
#define H_DIM   12
#define V_DIM   50257
#define DFF_DIM 3072
#define HS_DIM  (H_DIM*S_DIM)

// ------------------------- scratch (static device globals) -------------------------
__device__ float  g_meanWe[E_DIM];
__device__ float  g_bvec [B_DIM*E_DIM];
__device__ __half g_v    [(long)B_DIM*S_DIM*E_DIM];
__device__ __half g_WeH  [(long)V_DIM*E_DIM];
__device__ __half g_WpH  [(long)S_DIM*E_DIM];
__device__ __half g_w1H  [(long)DFF_DIM*E_DIM];
__device__ __half g_w2H  [(long)E_DIM*DFF_DIM];
__device__ __half g_WqT  [(long)H_DIM*E_DIM*E_DIM];
__device__ __half g_WkT  [(long)H_DIM*E_DIM*E_DIM];
__device__ __half g_WvT  [(long)H_DIM*E_DIM*E_DIM];
__device__ __half g_Q    [(long)H_DIM*S_DIM*E_DIM];
__device__ __half g_K    [(long)H_DIM*S_DIM*E_DIM];
__device__ __half g_attnT[(long)S_DIM*HS_DIM];
__device__ __half g_VtT  [(long)B_DIM*E_DIM*HS_DIM];
__device__ __half g_f    [(long)B_DIM*S_DIM*E_DIM];
__device__ __half g_h1   [(long)B_DIM*S_DIM*DFF_DIM];
__device__ __half g_f2   [(long)B_DIM*S_DIM*E_DIM];

// ------------------------- helpers -------------------------
// K-permutation within 32-blocks: stored position p holds logical k = PIT(p);
// logical k stored at position STAB(k). PIT = STAB^{-1}.
__device__ __forceinline__ int PIT(int p)  { return 2*(p>>3) + (p&1) + ((p>>1)&3)*8; }
__device__ __forceinline__ int STAB(int k) { return 8*((k&7)>>1) + (k&1) + (((k>>3)&1)<<1) + (((k>>4)&1)<<2); }

__device__ __forceinline__ uint32_t s2u(const void* p) {
    uint32_t a;
    asm("{ .reg .u64 t; cvta.to.shared.u64 t, %1; cvt.u32.u64 %0, t; }" : "=r"(a) : "l"(p));
    return a;
}
__device__ __forceinline__ void cpa16(uint32_t dst, const void* src, int szbytes) {
    asm volatile("cp.async.cg.shared.global [%0], [%1], 16, %2;" :: "r"(dst), "l"(src), "r"(szbytes));
}
#define CP_COMMIT()  asm volatile("cp.async.commit_group;" ::: "memory")
#define CP_WAIT(n)   asm volatile("cp.async.wait_group %0;" :: "n"(n) : "memory")

__device__ __forceinline__ void mma16(float* c, uint32_t a0, uint32_t a1, uint32_t a2, uint32_t a3,
                                      uint32_t b0, uint32_t b1) {
    asm volatile("mma.sync.aligned.m16n8k16.row.col.f32.f16.f16.f32 "
        "{%0,%1,%2,%3}, {%4,%5,%6,%7}, {%8,%9}, {%0,%1,%2,%3};"
        : "+f"(c[0]), "+f"(c[1]), "+f"(c[2]), "+f"(c[3])
        : "r"(a0), "r"(a1), "r"(a2), "r"(a3), "r"(b0), "r"(b1));
}

union F4 { float4 v; uint32_t u[4]; };

__device__ __forceinline__ void stv(float* p, float v)  { *p = v; }
__device__ __forceinline__ void stv(__half* p, float v) { *p = __float2half(v); }

// ------------------------- small kernels -------------------------
__global__ void zero_init_k() {
    int t = threadIdx.x;
    if (t < E_DIM) g_meanWe[t] = 0.0f;
    for (int i = t; i < B_DIM * E_DIM; i += 1024) g_bvec[i] = 0.0f;
}

__global__ void colmean_k(const float* __restrict__ W_e) {
    int e = blockIdx.x * 256 + threadIdx.x;
    int chunk = blockIdx.y;
    const int CH = (V_DIM + 63) / 64;
    int v0 = chunk * CH;
    int v1 = v0 + CH; if (v1 > V_DIM) v1 = V_DIM;
    float s = 0.0f;
    for (int v = v0; v < v1; v++) s += W_e[(long)v * E_DIM + e];
    atomicAdd(&g_meanWe[e], s * (1.0f / 50257.0f));
}

__global__ void convert_perm_k(const float* __restrict__ s, __half* __restrict__ d, long n) {
    long i = (long)blockIdx.x * blockDim.x + threadIdx.x;
    long stride = (long)gridDim.x * blockDim.x;
    for (; i < n; i += stride) {
        long blk = i & ~31L;
        d[i] = __float2half(s[blk + PIT((int)(i & 31))]);
    }
}

__global__ void embed_k(const int* __restrict__ x, const float* __restrict__ W_e) {
    long i = (long)blockIdx.x * blockDim.x + threadIdx.x;
    const long n = (long)B_DIM * S_DIM * E_DIM;
    if (i >= n) return;
    int p = (int)(i % E_DIM);
    long bs = i / E_DIM;
    int e = (p & ~31) + PIT(p & 31);
    g_v[i] = __float2half(W_e[(long)x[bs] * E_DIM + e] - g_meanWe[e]);
}

__global__ void bvec_k(const float* __restrict__ Blr) {
    int b = blockIdx.x;
    int chunk = blockIdx.y;
    int p = threadIdx.x;
    const __half* vb = g_v + (long)b * S_DIM * E_DIM + (long)chunk * 64 * E_DIM + p;
    float s = 0.0f;
    #pragma unroll 4
    for (int t = 0; t < 64; t++) s += __half2float(vb[(long)t * E_DIM]);
    int e = (p & ~31) + PIT(p & 31);
    atomicAdd(&g_bvec[b * E_DIM + e], s * Blr[0] * (1.0f / (float)S_DIM));
}

__global__ void transpose_head_k(const float* __restrict__ in, __half* __restrict__ out) {
    __shared__ float tile[32][33];
    int h = blockIdx.z;
    int i0 = blockIdx.y * 32, j0 = blockIdx.x * 32;
    const float* src = in + (long)h * E_DIM * E_DIM;
    __half* dst = out + (long)h * E_DIM * E_DIM;
    int tx = threadIdx.x, ty = threadIdx.y;
    #pragma unroll
    for (int r = 0; r < 32; r += 8)
        tile[ty + r][tx] = src[(long)(i0 + ty + r) * E_DIM + j0 + tx];
    __syncthreads();
    #pragma unroll
    for (int r = 0; r < 32; r += 8)
        dst[(long)(j0 + ty + r) * E_DIM + i0 + tx] = __float2half(tile[PIT(tx)][ty + r]);
}

__global__ void softmax_h(__half* __restrict__ attnT) {
    int q = blockIdx.x / H_DIM;
    int h = blockIdx.x % H_DIM;
    __half2* row = reinterpret_cast<__half2*>(attnT + (long)q * HS_DIM + (long)h * S_DIM);
    int tid = threadIdx.x;   // 256
    const float scale = 0.03608439182435161f;   // 1/sqrt(768)
    __half2 h0 = row[2 * tid], h1v = row[2 * tid + 1];
    float2 f0 = __half22float2(h0), f1 = __half22float2(h1v);
    float m = fmaxf(fmaxf(f0.x, f0.y), fmaxf(f1.x, f1.y));
    __shared__ float red[8];
    #pragma unroll
    for (int o = 16; o > 0; o >>= 1) m = fmaxf(m, __shfl_xor_sync(0xffffffffu, m, o));
    if ((tid & 31) == 0) red[tid >> 5] = m;
    __syncthreads();
    m = red[0];
    #pragma unroll
    for (int w = 1; w < 8; w++) m = fmaxf(m, red[w]);
    float e0 = expf(scale * (f0.x - m));
    float e1 = expf(scale * (f0.y - m));
    float e2 = expf(scale * (f1.x - m));
    float e3 = expf(scale * (f1.y - m));
    float s = e0 + e1 + e2 + e3;
    #pragma unroll
    for (int o = 16; o > 0; o >>= 1) s += __shfl_xor_sync(0xffffffffu, s, o);
    __syncthreads();
    if ((tid & 31) == 0) red[tid >> 5] = s;
    __syncthreads();
    s = 0.0f;
    #pragma unroll
    for (int w = 0; w < 8; w++) s += red[w];
    float inv = 1.0f / s;
    row[2 * tid]     = __floats2half2_rn(e0 * inv, e1 * inv);
    row[2 * tid + 1] = __floats2half2_rn(e2 * inv, e3 * inv);
}

// ------------------------- fp16 cp.async NT GEMM (K=128 per stage) -----------------
// C[m,n] = ((alpha * sum_k A[m,k]*B[n,k]) + bias[n]) [GELU] * storeScale
// Operands fp16, K-permuted in gmem. Block tile 128x128; each pipeline stage
// holds K=128 as two 64-K sub-tiles ([A0|B0|A1|B1], 16KB each). NS=3 stages
// (192KB smem). 512 threads, 16 warps (4x4), warp tile 32x32, mma.m16n8k16.
// smem row = 64 halfs (128B) = 8 chunks; logical chunk c at c ^ ((row&1)*4).
// ONE __syncthreads per 128-K stage (arrival + stage-reuse, distance 2).

#define NS 3
#define SUB_HALFS   16384           // 32KB: A 128x64 | B 128x64
#define STAGE_HALFS (2 * SUB_HALFS) // 64KB
#define GEMMH_SMEM  (NS * STAGE_HALFS * 2)   // 196608 B

template<bool GELU, bool PERM, typename OutT>
__global__ __launch_bounds__(512, 1)
void gemm_h(const __half* __restrict__ Ag, const __half* __restrict__ Bg,
            OutT* __restrict__ Cg,
            int M, int N, int K, int lda, int ldb, int ldc,
            long sA, long sB, long sC1, long sC2, int divA, int modB,
            const float* __restrict__ alphaPtr, int alphaMod, float alphaScale,
            const float* __restrict__ biasPtr, long biasStride, float storeScale)
{
    extern __shared__ __half smh[];

    int z = blockIdx.z;
    const __half* A = Ag + (long)(z / divA) * sA;
    const __half* B = Bg + (long)(z % modB) * sB;
    OutT* C = Cg + (long)(z / divA) * sC1 + (long)(z % modB) * sC2;
    float alpha = alphaScale;
    if (alphaPtr) alpha *= alphaPtr[(z / divA) % alphaMod];
    const float* bias = biasPtr ? (biasPtr + (long)z * biasStride) : nullptr;

    int bm = blockIdx.x * 128;
    int bn = blockIdx.y * 128;
    int tid = threadIdx.x;
    int warp = tid >> 5, lane = tid & 31;
    int wm = warp >> 2, wn = warp & 3;     // 4x4 warp grid
    int g = lane >> 2, t = lane & 3;
    int gx = (g & 1) << 2;                 // row-parity XOR for this thread's rows/cols

    // producer: row = tid>>2 (0..127), logical chunks lc and lc+4 per sub-tile
    int lrow = tid >> 2;
    int lc = tid & 3;
    int rpx = (lrow & 1) << 2;
    int am = bm + lrow;
    bool aok = am < M;
    const __half* abase = aok ? (A + (long)am * lda) : A;
    int nn = bn + lrow;
    bool bok = nn < N;
    const __half* bbase = bok ? (B + (long)nn * ldb) : B;
    int asz = aok ? 16 : 0, bsz = bok ? 16 : 0;

    uint32_t smb = s2u(smh);
    uint32_t dA0 = smb + (uint32_t)(lrow * 128 + ((lc      ^ rpx) << 4));
    uint32_t dA1 = smb + (uint32_t)(lrow * 128 + (((lc + 4) ^ rpx) << 4));
    uint32_t dB0 = dA0 + SUB_HALFS;        // bytes: B half of sub-tile (+32KB? no: halfs*2=32KB)
    uint32_t dB1 = dA1 + SUB_HALFS;        // SUB_HALFS halfs = 32768 B offset... (A sub is 16KB)

    // NOTE on offsets: addresses are BYTE addresses. A sub-tile = 8192 halfs = 16384 B.
    // Within a sub-tile: [A 16384 B][B 16384 B] => B offset = 16384 B = SUB_HALFS bytes? 
    // SUB_HALFS = 16384 (halfs) happens to equal the BYTE size of the A half. Used as bytes here.

    float acc[2][4][4];
    #pragma unroll
    for (int i = 0; i < 2; i++)
        #pragma unroll
        for (int j = 0; j < 4; j++)
            #pragma unroll
            for (int r = 0; r < 4; r++) acc[i][j][r] = 0.0f;

    int nt = K >> 7;     // K multiple of 128

    auto produce = [&](int stage) {
        uint32_t soff = (uint32_t)((stage % NS) * (STAGE_HALFS * 2));
        #pragma unroll
        for (int sub = 0; sub < 2; sub++) {
            uint32_t off = soff + sub * (SUB_HALFS * 2);
            int k0 = (stage << 7) + (sub << 6);
            cpa16(dA0 + off, abase + k0 + lc * 8,        asz);
            cpa16(dA1 + off, abase + k0 + (lc + 4) * 8,  asz);
            cpa16(dB0 + off, bbase + k0 + lc * 8,        bsz);
            cpa16(dB1 + off, bbase + k0 + (lc + 4) * 8,  bsz);
        }
    };

    #pragma unroll
    for (int p = 0; p < NS - 1; p++) { produce(p); CP_COMMIT(); }

    for (int it = 0; it < nt; it++) {
        int s = it % NS;
        CP_WAIT(NS - 2);
        __syncthreads();     // single barrier per 128-K stage

        if (it + NS - 1 < nt) produce(it + NS - 1);
        CP_COMMIT();

        #pragma unroll
        for (int sub = 0; sub < 2; sub++) {
            const __half* As = smh + s * STAGE_HALFS + sub * SUB_HALFS;
            const __half* Bs = As + 8192;

            #pragma unroll
            for (int h = 0; h < 2; h++) {
                int cx = (t + 4 * h) ^ gx;     // stored chunk index for this thread
                F4 a[2][2], b[4];
                #pragma unroll
                for (int i = 0; i < 2; i++) {
                    int r0 = wm * 32 + i * 16 + g;
                    a[i][0].v = *reinterpret_cast<const float4*>(As + r0 * 64 + cx * 8);
                    a[i][1].v = *reinterpret_cast<const float4*>(As + (r0 + 8) * 64 + cx * 8);
                }
                #pragma unroll
                for (int j = 0; j < 4; j++) {
                    int cb = wn * 32 + j * 8 + g;
                    b[j].v = *reinterpret_cast<const float4*>(Bs + cb * 64 + cx * 8);
                }
                #pragma unroll
                for (int i = 0; i < 2; i++)
                    #pragma unroll
                    for (int j = 0; j < 4; j++) {
                        mma16(acc[i][j], a[i][0].u[0], a[i][1].u[0], a[i][0].u[1], a[i][1].u[1],
                              b[j].u[0], b[j].u[1]);
                        mma16(acc[i][j], a[i][0].u[2], a[i][1].u[2], a[i][0].u[3], a[i][1].u[3],
                              b[j].u[2], b[j].u[3]);
                    }
            }
        }
    }

    // ---- epilogue ----
    #pragma unroll
    for (int i = 0; i < 2; i++) {
        #pragma unroll
        for (int j = 0; j < 4; j++) {
            int nl = wn * 32 + j * 8 + 2 * t;               // logical col in tile
            int n0 = bn + nl;
            int sn = PERM ? (bn + (nl & ~31) + STAB(nl & 31)) : n0;
            #pragma unroll
            for (int half = 0; half < 2; half++) {
                int m = bm + wm * 32 + i * 16 + g + half * 8;
                if (m >= M) continue;
                float v0 = acc[i][j][half * 2 + 0] * alpha;
                float v1 = acc[i][j][half * 2 + 1] * alpha;
                if (bias) { if (n0 < N) v0 += bias[n0]; if (n0 + 1 < N) v1 += bias[n0 + 1]; }
                if (GELU) {
                    v0 = 0.5f * v0 * (1.0f + erff(v0 * 0.70710678118654752f));
                    v1 = 0.5f * v1 * (1.0f + erff(v1 * 0.70710678118654752f));
                }
                v0 *= storeScale; v1 *= storeScale;
                OutT* crow = C + (long)m * ldc;
                if (n0 < N)     stv(crow + sn,     v0);
                if (n0 + 1 < N) stv(crow + sn + 1, v1);
            }
        }
    }
}

// ------------------------- launch -------------------------
extern "C" void kernel_launch(void* const* d_in, const int* in_sizes, int n_in,
                              void* d_out, int out_size) {
    (void)in_sizes; (void)n_in; (void)out_size;
    const int*   x     = (const int*)  d_in[0];
    const float* W_e   = (const float*)d_in[1];
    const float* W_p   = (const float*)d_in[2];
    const float* W_q   = (const float*)d_in[3];
    const float* W_k   = (const float*)d_in[4];
    const float* W_v   = (const float*)d_in[5];
    const float* A_lr  = (const float*)d_in[6];
    const float* B_lr  = (const float*)d_in[7];
    const float* ff_w1 = (const float*)d_in[8];
    const float* ff_w2 = (const float*)d_in[9];
    float* out = (float*)d_out;

    float *p_bvec;
    __half *p_v, *p_WeH, *p_WpH, *p_w1H, *p_w2H;
    __half *p_WqT, *p_WkT, *p_WvT, *p_Q, *p_K, *p_attnT, *p_VtT, *p_f, *p_h1, *p_f2;
    cudaGetSymbolAddress((void**)&p_bvec,  g_bvec);
    cudaGetSymbolAddress((void**)&p_v,     g_v);
    cudaGetSymbolAddress((void**)&p_WeH,   g_WeH);
    cudaGetSymbolAddress((void**)&p_WpH,   g_WpH);
    cudaGetSymbolAddress((void**)&p_w1H,   g_w1H);
    cudaGetSymbolAddress((void**)&p_w2H,   g_w2H);
    cudaGetSymbolAddress((void**)&p_WqT,   g_WqT);
    cudaGetSymbolAddress((void**)&p_WkT,   g_WkT);
    cudaGetSymbolAddress((void**)&p_WvT,   g_WvT);
    cudaGetSymbolAddress((void**)&p_Q,     g_Q);
    cudaGetSymbolAddress((void**)&p_K,     g_K);
    cudaGetSymbolAddress((void**)&p_attnT, g_attnT);
    cudaGetSymbolAddress((void**)&p_VtT,   g_VtT);
    cudaGetSymbolAddress((void**)&p_f,     g_f);
    cudaGetSymbolAddress((void**)&p_h1,    g_h1);
    cudaGetSymbolAddress((void**)&p_f2,    g_f2);

    static bool attr_done = false;
    if (!attr_done) {
        cudaFuncSetAttribute(gemm_h<false, true,  __half>, cudaFuncAttributeMaxDynamicSharedMemorySize, GEMMH_SMEM);
        cudaFuncSetAttribute(gemm_h<true,  true,  __half>, cudaFuncAttributeMaxDynamicSharedMemorySize, GEMMH_SMEM);
        cudaFuncSetAttribute(gemm_h<false, false, float >, cudaFuncAttributeMaxDynamicSharedMemorySize, GEMMH_SMEM);
        attr_done = true;
    }

    const int BIG = 1 << 30;
    const long EE = (long)E_DIM * E_DIM;
    const long HS = (long)HS_DIM;
    const long SE = (long)S_DIM * E_DIM;
    const float SS = 1024.0f, ISS = 1.0f / 1024.0f;

    zero_init_k<<<1, 1024>>>();
    { dim3 g(3, 64); colmean_k<<<g, 256>>>(W_e); }
    { long nv = (long)B_DIM * S_DIM * E_DIM;
      embed_k<<<(int)((nv + 255) / 256), 256>>>(x, W_e); }
    { dim3 g(B_DIM, 16); bvec_k<<<g, E_DIM>>>(B_lr); }

    convert_perm_k<<<4096, 256>>>(W_e,   p_WeH, (long)V_DIM * E_DIM);
    convert_perm_k<<<1024, 256>>>(W_p,   p_WpH, SE);
    convert_perm_k<<<1024, 256>>>(ff_w1, p_w1H, (long)DFF_DIM * E_DIM);
    convert_perm_k<<<1024, 256>>>(ff_w2, p_w2H, (long)E_DIM * DFF_DIM);

    { dim3 g(24, 24, 12), b(32, 8);
      transpose_head_k<<<g, b>>>(W_q, p_WqT);
      transpose_head_k<<<g, b>>>(W_k, p_WkT);
      transpose_head_k<<<g, b>>>(W_v, p_WvT); }

    // Q[h] = W_p[:1024] @ WqT[h]^T
    { dim3 g(8, 6, H_DIM);
      gemm_h<false, true, __half><<<g, 512, GEMMH_SMEM>>>(p_WpH, p_WqT, p_Q,
          S_DIM, E_DIM, E_DIM, E_DIM, E_DIM, E_DIM,
          0L, EE, SE, 0L, 1, BIG,
          nullptr, 1, 1.0f, nullptr, 0L, 1.0f); }
    // K[h] = W_p[:1024] @ WkT[h]^T
    { dim3 g(8, 6, H_DIM);
      gemm_h<false, true, __half><<<g, 512, GEMMH_SMEM>>>(p_WpH, p_WkT, p_K,
          S_DIM, E_DIM, E_DIM, E_DIM, E_DIM, E_DIM,
          0L, EE, SE, 0L, 1, BIG,
          nullptr, 1, 1.0f, nullptr, 0L, 1.0f); }
    // attnT[q, h*S+s] = Q[h] @ K[h]^T
    { dim3 g(8, 8, H_DIM);
      gemm_h<false, true, __half><<<g, 512, GEMMH_SMEM>>>(p_Q, p_K, p_attnT,
          S_DIM, S_DIM, E_DIM, E_DIM, E_DIM, HS_DIM,
          SE, SE, (long)S_DIM, 0L, 1, BIG,
          nullptr, 1, 1.0f, nullptr, 0L, 1.0f); }
    softmax_h<<<S_DIM * H_DIM, 256>>>(p_attnT);

    // VtT[b][e][h*S+s] = A_lr[h] * (WvT[h] @ v[b]^T); z = h*B + b
    { dim3 g(6, 8, H_DIM * B_DIM);
      gemm_h<false, true, __half><<<g, 512, GEMMH_SMEM>>>(p_WvT, p_v, p_VtT,
          E_DIM, S_DIM, E_DIM, E_DIM, E_DIM, HS_DIM,
          EE, SE, (long)S_DIM, (long)E_DIM * HS, B_DIM, B_DIM,
          A_lr, H_DIM, 1.0f, nullptr, 0L, 1.0f); }
    // f[b] = (attnT @ VtT[b]^T)/S + bvec[b]; stored x1024
    { dim3 g(8, 6, B_DIM);
      gemm_h<false, true, __half><<<g, 512, GEMMH_SMEM>>>(p_attnT, p_VtT, p_f,
          S_DIM, E_DIM, HS_DIM, HS_DIM, HS_DIM, E_DIM,
          0L, (long)E_DIM * HS, SE, 0L, 1, BIG,
          nullptr, 1, 1.0f / (float)S_DIM, p_bvec, (long)E_DIM, SS); }
    // h1 = gelu(f @ ff_w1^T); alpha undoes x1024; stored x1024
    { dim3 g(32, 24, 1);
      gemm_h<true, true, __half><<<g, 512, GEMMH_SMEM>>>(p_f, p_w1H, p_h1,
          B_DIM * S_DIM, DFF_DIM, E_DIM, E_DIM, E_DIM, DFF_DIM,
          0L, 0L, 0L, 0L, 1, BIG,
          nullptr, 1, ISS, nullptr, 0L, SS); }
    // f2 = h1 @ ff_w2^T; stored x1024
    { dim3 g(32, 6, 1);
      gemm_h<false, true, __half><<<g, 512, GEMMH_SMEM>>>(p_h1, p_w2H, p_f2,
          B_DIM * S_DIM, E_DIM, DFF_DIM, DFF_DIM, DFF_DIM, E_DIM,
          0L, 0L, 0L, 0L, 1, BIG,
          nullptr, 1, ISS, nullptr, 0L, SS); }
    // logits: M=4096 (f2 batch-contiguous), N=50257; alpha undoes x1024
    { dim3 g(32, 393, 1);
      gemm_h<false, false, float><<<g, 512, GEMMH_SMEM>>>(p_f2, p_WeH, out,
          B_DIM * S_DIM, V_DIM, E_DIM, E_DIM, E_DIM, V_DIM,
          0L, 0L, 0L, 0L, 1, BIG,
          nullptr, 1, ISS, nullptr, 0L, 1.0f); }
}

// round 16
// speedup vs baseline: 1.0062x; 1.0062x over previous
#include <cuda_runtime.h>
#include <cuda_fp16.h>
#include <math.h>
#include <stdint.h>

#define E_DIM   768
#define S_DIM   1024
#define B_DIM   4
#define H_DIM   12
#define V_DIM   50257
#define DFF_DIM 3072
#define HS_DIM  (H_DIM*S_DIM)

// ------------------------- scratch (static device globals) -------------------------
__device__ float  g_meanWe[E_DIM];
__device__ float  g_bvec [B_DIM*E_DIM];
__device__ __half g_v    [(long)B_DIM*S_DIM*E_DIM];
__device__ __half g_WeH  [(long)V_DIM*E_DIM];
__device__ __half g_WpH  [(long)S_DIM*E_DIM];
__device__ __half g_w1H  [(long)DFF_DIM*E_DIM];
__device__ __half g_w2H  [(long)E_DIM*DFF_DIM];
__device__ __half g_WqT  [(long)H_DIM*E_DIM*E_DIM];
__device__ __half g_WkT  [(long)H_DIM*E_DIM*E_DIM];
__device__ __half g_WvT  [(long)H_DIM*E_DIM*E_DIM];
__device__ __half g_Q    [(long)H_DIM*S_DIM*E_DIM];
__device__ __half g_K    [(long)H_DIM*S_DIM*E_DIM];
__device__ __half g_attnT[(long)S_DIM*HS_DIM];
__device__ __half g_VtT  [(long)B_DIM*E_DIM*HS_DIM];
__device__ __half g_f    [(long)B_DIM*S_DIM*E_DIM];
__device__ __half g_h1   [(long)B_DIM*S_DIM*DFF_DIM];
__device__ __half g_f2   [(long)B_DIM*S_DIM*E_DIM];

// ------------------------- helpers -------------------------
// K-permutation within 32-blocks: stored position p holds logical k = PIT(p);
// logical k stored at position STAB(k). PIT = STAB^{-1}.
__device__ __forceinline__ int PIT(int p)  { return 2*(p>>3) + (p&1) + ((p>>1)&3)*8; }
__device__ __forceinline__ int STAB(int k) { return 8*((k&7)>>1) + (k&1) + (((k>>3)&1)<<1) + (((k>>4)&1)<<2); }

__device__ __forceinline__ uint32_t s2u(const void* p) {
    uint32_t a;
    asm("{ .reg .u64 t; cvta.to.shared.u64 t, %1; cvt.u32.u64 %0, t; }" : "=r"(a) : "l"(p));
    return a;
}
__device__ __forceinline__ void cpa16(uint32_t dst, const void* src, int szbytes) {
    asm volatile("cp.async.cg.shared.global [%0], [%1], 16, %2;" :: "r"(dst), "l"(src), "r"(szbytes));
}
#define CP_COMMIT()  asm volatile("cp.async.commit_group;" ::: "memory")
#define CP_WAIT(n)   asm volatile("cp.async.wait_group %0;" :: "n"(n) : "memory")

__device__ __forceinline__ void mma16(float* c, uint32_t a0, uint32_t a1, uint32_t a2, uint32_t a3,
                                      uint32_t b0, uint32_t b1) {
    asm volatile("mma.sync.aligned.m16n8k16.row.col.f32.f16.f16.f32 "
        "{%0,%1,%2,%3}, {%4,%5,%6,%7}, {%8,%9}, {%0,%1,%2,%3};"
        : "+f"(c[0]), "+f"(c[1]), "+f"(c[2]), "+f"(c[3])
        : "r"(a0), "r"(a1), "r"(a2), "r"(a3), "r"(b0), "r"(b1));
}

union F4 { float4 v; uint32_t u[4]; };

__device__ __forceinline__ void stv(float* p, float v)  { *p = v; }
__device__ __forceinline__ void stv(__half* p, float v) { *p = __float2half(v); }

// ------------------------- small kernels -------------------------
__global__ void zero_init_k() {
    int t = threadIdx.x;
    if (t < E_DIM) g_meanWe[t] = 0.0f;
    for (int i = t; i < B_DIM * E_DIM; i += 1024) g_bvec[i] = 0.0f;
}

__global__ void colmean_k(const float* __restrict__ W_e) {
    int e = blockIdx.x * 256 + threadIdx.x;
    int chunk = blockIdx.y;
    const int CH = (V_DIM + 63) / 64;
    int v0 = chunk * CH;
    int v1 = v0 + CH; if (v1 > V_DIM) v1 = V_DIM;
    float s = 0.0f;
    for (int v = v0; v < v1; v++) s += W_e[(long)v * E_DIM + e];
    atomicAdd(&g_meanWe[e], s * (1.0f / 50257.0f));
}

__global__ void convert_perm_k(const float* __restrict__ s, __half* __restrict__ d, long n) {
    long i = (long)blockIdx.x * blockDim.x + threadIdx.x;
    long stride = (long)gridDim.x * blockDim.x;
    for (; i < n; i += stride) {
        long blk = i & ~31L;
        d[i] = __float2half(s[blk + PIT((int)(i & 31))]);
    }
}

__global__ void embed_k(const int* __restrict__ x, const float* __restrict__ W_e) {
    long i = (long)blockIdx.x * blockDim.x + threadIdx.x;
    const long n = (long)B_DIM * S_DIM * E_DIM;
    if (i >= n) return;
    int p = (int)(i % E_DIM);
    long bs = i / E_DIM;
    int e = (p & ~31) + PIT(p & 31);
    g_v[i] = __float2half(W_e[(long)x[bs] * E_DIM + e] - g_meanWe[e]);
}

__global__ void bvec_k(const float* __restrict__ Blr) {
    int b = blockIdx.x;
    int chunk = blockIdx.y;
    int p = threadIdx.x;
    const __half* vb = g_v + (long)b * S_DIM * E_DIM + (long)chunk * 64 * E_DIM + p;
    float s = 0.0f;
    #pragma unroll 4
    for (int t = 0; t < 64; t++) s += __half2float(vb[(long)t * E_DIM]);
    int e = (p & ~31) + PIT(p & 31);
    atomicAdd(&g_bvec[b * E_DIM + e], s * Blr[0] * (1.0f / (float)S_DIM));
}

__global__ void transpose_head_k(const float* __restrict__ in, __half* __restrict__ out) {
    __shared__ float tile[32][33];
    int h = blockIdx.z;
    int i0 = blockIdx.y * 32, j0 = blockIdx.x * 32;
    const float* src = in + (long)h * E_DIM * E_DIM;
    __half* dst = out + (long)h * E_DIM * E_DIM;
    int tx = threadIdx.x, ty = threadIdx.y;
    #pragma unroll
    for (int r = 0; r < 32; r += 8)
        tile[ty + r][tx] = src[(long)(i0 + ty + r) * E_DIM + j0 + tx];
    __syncthreads();
    #pragma unroll
    for (int r = 0; r < 32; r += 8)
        dst[(long)(j0 + ty + r) * E_DIM + i0 + tx] = __float2half(tile[PIT(tx)][ty + r]);
}

__global__ void softmax_h(__half* __restrict__ attnT) {
    int q = blockIdx.x / H_DIM;
    int h = blockIdx.x % H_DIM;
    __half2* row = reinterpret_cast<__half2*>(attnT + (long)q * HS_DIM + (long)h * S_DIM);
    int tid = threadIdx.x;   // 256
    const float scale = 0.03608439182435161f;   // 1/sqrt(768)
    __half2 h0 = row[2 * tid], h1v = row[2 * tid + 1];
    float2 f0 = __half22float2(h0), f1 = __half22float2(h1v);
    float m = fmaxf(fmaxf(f0.x, f0.y), fmaxf(f1.x, f1.y));
    __shared__ float red[8];
    #pragma unroll
    for (int o = 16; o > 0; o >>= 1) m = fmaxf(m, __shfl_xor_sync(0xffffffffu, m, o));
    if ((tid & 31) == 0) red[tid >> 5] = m;
    __syncthreads();
    m = red[0];
    #pragma unroll
    for (int w = 1; w < 8; w++) m = fmaxf(m, red[w]);
    float e0 = expf(scale * (f0.x - m));
    float e1 = expf(scale * (f0.y - m));
    float e2 = expf(scale * (f1.x - m));
    float e3 = expf(scale * (f1.y - m));
    float s = e0 + e1 + e2 + e3;
    #pragma unroll
    for (int o = 16; o > 0; o >>= 1) s += __shfl_xor_sync(0xffffffffu, s, o);
    __syncthreads();
    if ((tid & 31) == 0) red[tid >> 5] = s;
    __syncthreads();
    s = 0.0f;
    #pragma unroll
    for (int w = 0; w < 8; w++) s += red[w];
    float inv = 1.0f / s;
    row[2 * tid]     = __floats2half2_rn(e0 * inv, e1 * inv);
    row[2 * tid + 1] = __floats2half2_rn(e2 * inv, e3 * inv);
}

// ------------------------- fp16 cp.async NT GEMM (BM=64, 2 CTAs/SM) ---------------
// C[m,n] = ((alpha * sum_k A[m,k]*B[n,k]) + bias[n]) [GELU] * storeScale
// Operands fp16, K-permuted in gmem. Block tile 64x128x64(halfs).
// 256 threads, 8 warps (2x4), warp tile 32x32, mma.m16n8k16.
// NS=4 stages x 24KB = 96KB smem -> 2 CTAs/SM (launch_bounds(256,2)):
// the second CTA hides the post-barrier LDS fill bubble of the first.
// smem row = 64 halfs (128B) = 8 chunks; logical chunk c at c ^ ((row&1)*4).
// Single __syncthreads per K-tile (arrival + stage-reuse, distance 3).

#define NS 4
#define A_BYTES     8192            // 64 rows x 128 B
#define B_BYTES     16384           // 128 rows x 128 B
#define STAGE_BYTES (A_BYTES + B_BYTES)   // 24576
#define GEMMH_SMEM  (NS * STAGE_BYTES)    // 98304

template<bool GELU, bool PERM, typename OutT>
__global__ __launch_bounds__(256, 2)
void gemm_h(const __half* __restrict__ Ag, const __half* __restrict__ Bg,
            OutT* __restrict__ Cg,
            int M, int N, int K, int lda, int ldb, int ldc,
            long sA, long sB, long sC1, long sC2, int divA, int modB,
            const float* __restrict__ alphaPtr, int alphaMod, float alphaScale,
            const float* __restrict__ biasPtr, long biasStride, float storeScale)
{
    extern __shared__ __half smh[];

    int z = blockIdx.z;
    const __half* A = Ag + (long)(z / divA) * sA;
    const __half* B = Bg + (long)(z % modB) * sB;
    OutT* C = Cg + (long)(z / divA) * sC1 + (long)(z % modB) * sC2;
    float alpha = alphaScale;
    if (alphaPtr) alpha *= alphaPtr[(z / divA) % alphaMod];
    const float* bias = biasPtr ? (biasPtr + (long)z * biasStride) : nullptr;

    int bm = blockIdx.x * 64;
    int bn = blockIdx.y * 128;
    int tid = threadIdx.x;
    int warp = tid >> 5, lane = tid & 31;
    int wm = warp >> 2, wn = warp & 3;     // 2x4 warp grid
    int g = lane >> 2, t = lane & 3;
    int gx = (g & 1) << 2;                 // row-parity XOR for this thread's rows/cols

    // ---- producers ----
    // A: row = tid>>2 (0..63), logical chunks lc and lc+4
    int lrow = tid >> 2;
    int lc = tid & 3;
    int rpx = (lrow & 1) << 2;
    int am = bm + lrow;
    bool aok = am < M;
    const __half* abase = aok ? (A + (long)am * lda) : A;
    int asz = aok ? 16 : 0;
    // B: row = tid>>1 (0..127), logical chunks bc0..bc0+3
    int brow = tid >> 1;
    int bc0 = (tid & 1) * 4;
    int brpx = (brow & 1) << 2;
    int nn = bn + brow;
    bool bok = nn < N;
    const __half* bbase = bok ? (B + (long)nn * ldb) : B;
    int bsz = bok ? 16 : 0;

    uint32_t smb = s2u(smh);
    uint32_t dA0 = smb + (uint32_t)(lrow * 128 + ((lc      ^ rpx) << 4));
    uint32_t dA1 = smb + (uint32_t)(lrow * 128 + (((lc + 4) ^ rpx) << 4));
    uint32_t dB[4];
    #pragma unroll
    for (int q = 0; q < 4; q++)
        dB[q] = smb + A_BYTES + (uint32_t)(brow * 128 + (((bc0 + q) ^ brpx) << 4));

    float acc[2][4][4];
    #pragma unroll
    for (int i = 0; i < 2; i++)
        #pragma unroll
        for (int j = 0; j < 4; j++)
            #pragma unroll
            for (int r = 0; r < 4; r++) acc[i][j][r] = 0.0f;

    int nt = K >> 6;     // K multiple of 64

    auto produce = [&](int tile) {
        uint32_t off = (uint32_t)((tile & (NS - 1)) * STAGE_BYTES);
        int k0 = tile << 6;
        cpa16(dA0 + off, abase + k0 + lc * 8,       asz);
        cpa16(dA1 + off, abase + k0 + (lc + 4) * 8, asz);
        #pragma unroll
        for (int q = 0; q < 4; q++)
            cpa16(dB[q] + off, bbase + k0 + (bc0 + q) * 8, bsz);
    };

    #pragma unroll
    for (int p = 0; p < NS - 1; p++) { produce(p); CP_COMMIT(); }

    for (int it = 0; it < nt; it++) {
        int s = it & (NS - 1);
        CP_WAIT(NS - 2);
        __syncthreads();     // single barrier: arrival + stage-reuse ordering

        if (it + NS - 1 < nt) produce(it + NS - 1);
        CP_COMMIT();

        const __half* As = smh + s * (STAGE_BYTES / 2);
        const __half* Bs = As + (A_BYTES / 2);

        #pragma unroll
        for (int h = 0; h < 2; h++) {
            int cx = (t + 4 * h) ^ gx;     // stored chunk index for this thread
            F4 a[2][2], b[4];
            #pragma unroll
            for (int i = 0; i < 2; i++) {
                int r0 = wm * 32 + i * 16 + g;
                a[i][0].v = *reinterpret_cast<const float4*>(As + r0 * 64 + cx * 8);
                a[i][1].v = *reinterpret_cast<const float4*>(As + (r0 + 8) * 64 + cx * 8);
            }
            #pragma unroll
            for (int j = 0; j < 4; j++) {
                int cb = wn * 32 + j * 8 + g;
                b[j].v = *reinterpret_cast<const float4*>(Bs + cb * 64 + cx * 8);
            }
            #pragma unroll
            for (int i = 0; i < 2; i++)
                #pragma unroll
                for (int j = 0; j < 4; j++) {
                    mma16(acc[i][j], a[i][0].u[0], a[i][1].u[0], a[i][0].u[1], a[i][1].u[1],
                          b[j].u[0], b[j].u[1]);
                    mma16(acc[i][j], a[i][0].u[2], a[i][1].u[2], a[i][0].u[3], a[i][1].u[3],
                          b[j].u[2], b[j].u[3]);
                }
        }
    }

    // ---- epilogue ----
    #pragma unroll
    for (int i = 0; i < 2; i++) {
        #pragma unroll
        for (int j = 0; j < 4; j++) {
            int nl = wn * 32 + j * 8 + 2 * t;               // logical col in tile
            int n0 = bn + nl;
            int sn = PERM ? (bn + (nl & ~31) + STAB(nl & 31)) : n0;
            #pragma unroll
            for (int half = 0; half < 2; half++) {
                int m = bm + wm * 32 + i * 16 + g + half * 8;
                if (m >= M) continue;
                float v0 = acc[i][j][half * 2 + 0] * alpha;
                float v1 = acc[i][j][half * 2 + 1] * alpha;
                if (bias) { if (n0 < N) v0 += bias[n0]; if (n0 + 1 < N) v1 += bias[n0 + 1]; }
                if (GELU) {
                    v0 = 0.5f * v0 * (1.0f + erff(v0 * 0.70710678118654752f));
                    v1 = 0.5f * v1 * (1.0f + erff(v1 * 0.70710678118654752f));
                }
                v0 *= storeScale; v1 *= storeScale;
                OutT* crow = C + (long)m * ldc;
                if (n0 < N)     stv(crow + sn,     v0);
                if (n0 + 1 < N) stv(crow + sn + 1, v1);
            }
        }
    }
}

// ------------------------- launch -------------------------
extern "C" void kernel_launch(void* const* d_in, const int* in_sizes, int n_in,
                              void* d_out, int out_size) {
    (void)in_sizes; (void)n_in; (void)out_size;
    const int*   x     = (const int*)  d_in[0];
    const float* W_e   = (const float*)d_in[1];
    const float* W_p   = (const float*)d_in[2];
    const float* W_q   = (const float*)d_in[3];
    const float* W_k   = (const float*)d_in[4];
    const float* W_v   = (const float*)d_in[5];
    const float* A_lr  = (const float*)d_in[6];
    const float* B_lr  = (const float*)d_in[7];
    const float* ff_w1 = (const float*)d_in[8];
    const float* ff_w2 = (const float*)d_in[9];
    float* out = (float*)d_out;

    float *p_bvec;
    __half *p_v, *p_WeH, *p_WpH, *p_w1H, *p_w2H;
    __half *p_WqT, *p_WkT, *p_WvT, *p_Q, *p_K, *p_attnT, *p_VtT, *p_f, *p_h1, *p_f2;
    cudaGetSymbolAddress((void**)&p_bvec,  g_bvec);
    cudaGetSymbolAddress((void**)&p_v,     g_v);
    cudaGetSymbolAddress((void**)&p_WeH,   g_WeH);
    cudaGetSymbolAddress((void**)&p_WpH,   g_WpH);
    cudaGetSymbolAddress((void**)&p_w1H,   g_w1H);
    cudaGetSymbolAddress((void**)&p_w2H,   g_w2H);
    cudaGetSymbolAddress((void**)&p_WqT,   g_WqT);
    cudaGetSymbolAddress((void**)&p_WkT,   g_WkT);
    cudaGetSymbolAddress((void**)&p_WvT,   g_WvT);
    cudaGetSymbolAddress((void**)&p_Q,     g_Q);
    cudaGetSymbolAddress((void**)&p_K,     g_K);
    cudaGetSymbolAddress((void**)&p_attnT, g_attnT);
    cudaGetSymbolAddress((void**)&p_VtT,   g_VtT);
    cudaGetSymbolAddress((void**)&p_f,     g_f);
    cudaGetSymbolAddress((void**)&p_h1,    g_h1);
    cudaGetSymbolAddress((void**)&p_f2,    g_f2);

    static bool attr_done = false;
    if (!attr_done) {
        cudaFuncSetAttribute(gemm_h<false, true,  __half>, cudaFuncAttributeMaxDynamicSharedMemorySize, GEMMH_SMEM);
        cudaFuncSetAttribute(gemm_h<true,  true,  __half>, cudaFuncAttributeMaxDynamicSharedMemorySize, GEMMH_SMEM);
        cudaFuncSetAttribute(gemm_h<false, false, float >, cudaFuncAttributeMaxDynamicSharedMemorySize, GEMMH_SMEM);
        attr_done = true;
    }

    const int BIG = 1 << 30;
    const long EE = (long)E_DIM * E_DIM;
    const long HS = (long)HS_DIM;
    const long SE = (long)S_DIM * E_DIM;
    const float SS = 1024.0f, ISS = 1.0f / 1024.0f;

    zero_init_k<<<1, 1024>>>();
    { dim3 g(3, 64); colmean_k<<<g, 256>>>(W_e); }
    { long nv = (long)B_DIM * S_DIM * E_DIM;
      embed_k<<<(int)((nv + 255) / 256), 256>>>(x, W_e); }
    { dim3 g(B_DIM, 16); bvec_k<<<g, E_DIM>>>(B_lr); }

    convert_perm_k<<<4096, 256>>>(W_e,   p_WeH, (long)V_DIM * E_DIM);
    convert_perm_k<<<1024, 256>>>(W_p,   p_WpH, SE);
    convert_perm_k<<<1024, 256>>>(ff_w1, p_w1H, (long)DFF_DIM * E_DIM);
    convert_perm_k<<<1024, 256>>>(ff_w2, p_w2H, (long)E_DIM * DFF_DIM);

    { dim3 g(24, 24, 12), b(32, 8);
      transpose_head_k<<<g, b>>>(W_q, p_WqT);
      transpose_head_k<<<g, b>>>(W_k, p_WkT);
      transpose_head_k<<<g, b>>>(W_v, p_WvT); }

    // Q[h] = W_p[:1024] @ WqT[h]^T
    { dim3 g(16, 6, H_DIM);
      gemm_h<false, true, __half><<<g, 256, GEMMH_SMEM>>>(p_WpH, p_WqT, p_Q,
          S_DIM, E_DIM, E_DIM, E_DIM, E_DIM, E_DIM,
          0L, EE, SE, 0L, 1, BIG,
          nullptr, 1, 1.0f, nullptr, 0L, 1.0f); }
    // K[h] = W_p[:1024] @ WkT[h]^T
    { dim3 g(16, 6, H_DIM);
      gemm_h<false, true, __half><<<g, 256, GEMMH_SMEM>>>(p_WpH, p_WkT, p_K,
          S_DIM, E_DIM, E_DIM, E_DIM, E_DIM, E_DIM,
          0L, EE, SE, 0L, 1, BIG,
          nullptr, 1, 1.0f, nullptr, 0L, 1.0f); }
    // attnT[q, h*S+s] = Q[h] @ K[h]^T
    { dim3 g(16, 8, H_DIM);
      gemm_h<false, true, __half><<<g, 256, GEMMH_SMEM>>>(p_Q, p_K, p_attnT,
          S_DIM, S_DIM, E_DIM, E_DIM, E_DIM, HS_DIM,
          SE, SE, (long)S_DIM, 0L, 1, BIG,
          nullptr, 1, 1.0f, nullptr, 0L, 1.0f); }
    softmax_h<<<S_DIM * H_DIM, 256>>>(p_attnT);

    // VtT[b][e][h*S+s] = A_lr[h] * (WvT[h] @ v[b]^T); z = h*B + b
    { dim3 g(12, 8, H_DIM * B_DIM);
      gemm_h<false, true, __half><<<g, 256, GEMMH_SMEM>>>(p_WvT, p_v, p_VtT,
          E_DIM, S_DIM, E_DIM, E_DIM, E_DIM, HS_DIM,
          EE, SE, (long)S_DIM, (long)E_DIM * HS, B_DIM, B_DIM,
          A_lr, H_DIM, 1.0f, nullptr, 0L, 1.0f); }
    // f[b] = (attnT @ VtT[b]^T)/S + bvec[b]; stored x1024
    { dim3 g(16, 6, B_DIM);
      gemm_h<false, true, __half><<<g, 256, GEMMH_SMEM>>>(p_attnT, p_VtT, p_f,
          S_DIM, E_DIM, HS_DIM, HS_DIM, HS_DIM, E_DIM,
          0L, (long)E_DIM * HS, SE, 0L, 1, BIG,
          nullptr, 1, 1.0f / (float)S_DIM, p_bvec, (long)E_DIM, SS); }
    // h1 = gelu(f @ ff_w1^T); alpha undoes x1024; stored x1024
    { dim3 g(64, 24, 1);
      gemm_h<true, true, __half><<<g, 256, GEMMH_SMEM>>>(p_f, p_w1H, p_h1,
          B_DIM * S_DIM, DFF_DIM, E_DIM, E_DIM, E_DIM, DFF_DIM,
          0L, 0L, 0L, 0L, 1, BIG,
          nullptr, 1, ISS, nullptr, 0L, SS); }
    // f2 = h1 @ ff_w2^T; stored x1024
    { dim3 g(64, 6, 1);
      gemm_h<false, true, __half><<<g, 256, GEMMH_SMEM>>>(p_h1, p_w2H, p_f2,
          B_DIM * S_DIM, E_DIM, DFF_DIM, DFF_DIM, DFF_DIM, E_DIM,
          0L, 0L, 0L, 0L, 1, BIG,
          nullptr, 1, ISS, nullptr, 0L, SS); }
    // logits: M=4096 (f2 batch-contiguous), N=50257; alpha undoes x1024
    { dim3 g(64, 393, 1);
      gemm_h<false, false, float><<<g, 256, GEMMH_SMEM>>>(p_f2, p_WeH, out,
          B_DIM * S_DIM, V_DIM, E_DIM, E_DIM, E_DIM, V_DIM,
          0L, 0L, 0L, 0L, 1, BIG,
          nullptr, 1, ISS, nullptr, 0L, 1.0f); }
}

// round 17
// speedup vs baseline: 1.0597x; 1.0532x over previous
#include <cuda_runtime.h>
#include <cuda_fp16.h>
#include <math.h>
#include <stdint.h>

#define E_DIM   768
#define S_DIM   1024
#define B_DIM   4
#define H_DIM   12
#define V_DIM   50257
#define DFF_DIM 3072
#define HS_DIM  (H_DIM*S_DIM)
#define SE_L    ((long)S_DIM*E_DIM)

// ------------------------- scratch (static device globals) -------------------------
__device__ float  g_meanWe[E_DIM];
__device__ float  g_bvec [B_DIM*E_DIM];
__device__ __half g_v    [(long)B_DIM*S_DIM*E_DIM];
__device__ __half g_WeH  [(long)V_DIM*E_DIM];
__device__ __half g_WpH  [(long)S_DIM*E_DIM];
__device__ __half g_w1H  [(long)DFF_DIM*E_DIM];
__device__ __half g_w2H  [(long)E_DIM*DFF_DIM];
__device__ __half g_WqkT [(long)2*H_DIM*E_DIM*E_DIM];    // WqT heads 0-11, WkT heads 12-23
__device__ __half g_WvT  [(long)H_DIM*E_DIM*E_DIM];
__device__ __half g_QK   [(long)2*H_DIM*S_DIM*E_DIM];    // Q heads 0-11, K heads 12-23
__device__ __half g_attnT[(long)S_DIM*HS_DIM];
__device__ __half g_VtT  [(long)B_DIM*E_DIM*HS_DIM];
__device__ float  g_fpart[(long)12*S_DIM*E_DIM];         // 3 K-splits x 4 batches
__device__ __half g_f    [(long)B_DIM*S_DIM*E_DIM];
__device__ __half g_h1   [(long)B_DIM*S_DIM*DFF_DIM];
__device__ float  g_f2part[(long)2*B_DIM*S_DIM*E_DIM];   // 2 K-splits
__device__ __half g_f2   [(long)B_DIM*S_DIM*E_DIM];

// ------------------------- helpers -------------------------
// K-permutation within 32-blocks: stored position p holds logical k = PIT(p);
// logical k stored at position STAB(k). PIT = STAB^{-1}.
__device__ __forceinline__ int PIT(int p)  { return 2*(p>>3) + (p&1) + ((p>>1)&3)*8; }
__device__ __forceinline__ int STAB(int k) { return 8*((k&7)>>1) + (k&1) + (((k>>3)&1)<<1) + (((k>>4)&1)<<2); }

__device__ __forceinline__ uint32_t s2u(const void* p) {
    uint32_t a;
    asm("{ .reg .u64 t; cvta.to.shared.u64 t, %1; cvt.u32.u64 %0, t; }" : "=r"(a) : "l"(p));
    return a;
}
__device__ __forceinline__ void cpa16(uint32_t dst, const void* src, int szbytes) {
    asm volatile("cp.async.cg.shared.global [%0], [%1], 16, %2;" :: "r"(dst), "l"(src), "r"(szbytes));
}
#define CP_COMMIT()  asm volatile("cp.async.commit_group;" ::: "memory")
#define CP_WAIT(n)   asm volatile("cp.async.wait_group %0;" :: "n"(n) : "memory")

__device__ __forceinline__ void mma16(float* c, uint32_t a0, uint32_t a1, uint32_t a2, uint32_t a3,
                                      uint32_t b0, uint32_t b1) {
    asm volatile("mma.sync.aligned.m16n8k16.row.col.f32.f16.f16.f32 "
        "{%0,%1,%2,%3}, {%4,%5,%6,%7}, {%8,%9}, {%0,%1,%2,%3};"
        : "+f"(c[0]), "+f"(c[1]), "+f"(c[2]), "+f"(c[3])
        : "r"(a0), "r"(a1), "r"(a2), "r"(a3), "r"(b0), "r"(b1));
}

union F4 { float4 v; uint32_t u[4]; };

__device__ __forceinline__ void stv(float* p, float v)  { *p = v; }
__device__ __forceinline__ void stv(__half* p, float v) { *p = __float2half(v); }

// ------------------------- small kernels -------------------------
__global__ void zero_init_k() {
    int t = threadIdx.x;
    if (t < E_DIM) g_meanWe[t] = 0.0f;
    for (int i = t; i < B_DIM * E_DIM; i += 1024) g_bvec[i] = 0.0f;
}

__global__ void colmean_k(const float* __restrict__ W_e) {
    int e = blockIdx.x * 256 + threadIdx.x;
    int chunk = blockIdx.y;
    const int CH = (V_DIM + 63) / 64;
    int v0 = chunk * CH;
    int v1 = v0 + CH; if (v1 > V_DIM) v1 = V_DIM;
    float s = 0.0f;
    for (int v = v0; v < v1; v++) s += W_e[(long)v * E_DIM + e];
    atomicAdd(&g_meanWe[e], s * (1.0f / 50257.0f));
}

__global__ void convert_perm_k(const float* __restrict__ s, __half* __restrict__ d, long n) {
    long i = (long)blockIdx.x * blockDim.x + threadIdx.x;
    long stride = (long)gridDim.x * blockDim.x;
    for (; i < n; i += stride) {
        long blk = i & ~31L;
        d[i] = __float2half(s[blk + PIT((int)(i & 31))]);
    }
}

__global__ void embed_k(const int* __restrict__ x, const float* __restrict__ W_e) {
    long i = (long)blockIdx.x * blockDim.x + threadIdx.x;
    const long n = (long)B_DIM * S_DIM * E_DIM;
    if (i >= n) return;
    int p = (int)(i % E_DIM);
    long bs = i / E_DIM;
    int e = (p & ~31) + PIT(p & 31);
    g_v[i] = __float2half(W_e[(long)x[bs] * E_DIM + e] - g_meanWe[e]);
}

__global__ void bvec_k(const float* __restrict__ Blr) {
    int b = blockIdx.x;
    int chunk = blockIdx.y;
    int p = threadIdx.x;
    const __half* vb = g_v + (long)b * S_DIM * E_DIM + (long)chunk * 64 * E_DIM + p;
    float s = 0.0f;
    #pragma unroll 4
    for (int t = 0; t < 64; t++) s += __half2float(vb[(long)t * E_DIM]);
    int e = (p & ~31) + PIT(p & 31);
    atomicAdd(&g_bvec[b * E_DIM + e], s * Blr[0] * (1.0f / (float)S_DIM));
}

__global__ void transpose_head_k(const float* __restrict__ in, __half* __restrict__ out) {
    __shared__ float tile[32][33];
    int h = blockIdx.z;
    int i0 = blockIdx.y * 32, j0 = blockIdx.x * 32;
    const float* src = in + (long)h * E_DIM * E_DIM;
    __half* dst = out + (long)h * E_DIM * E_DIM;
    int tx = threadIdx.x, ty = threadIdx.y;
    #pragma unroll
    for (int r = 0; r < 32; r += 8)
        tile[ty + r][tx] = src[(long)(i0 + ty + r) * E_DIM + j0 + tx];
    __syncthreads();
    #pragma unroll
    for (int r = 0; r < 32; r += 8)
        dst[(long)(j0 + ty + r) * E_DIM + i0 + tx] = __float2half(tile[PIT(tx)][ty + r]);
}

__global__ void softmax_h(__half* __restrict__ attnT) {
    int q = blockIdx.x / H_DIM;
    int h = blockIdx.x % H_DIM;
    __half2* row = reinterpret_cast<__half2*>(attnT + (long)q * HS_DIM + (long)h * S_DIM);
    int tid = threadIdx.x;   // 256
    const float scale = 0.03608439182435161f;   // 1/sqrt(768)
    __half2 h0 = row[2 * tid], h1v = row[2 * tid + 1];
    float2 f0 = __half22float2(h0), f1 = __half22float2(h1v);
    float m = fmaxf(fmaxf(f0.x, f0.y), fmaxf(f1.x, f1.y));
    __shared__ float red[8];
    #pragma unroll
    for (int o = 16; o > 0; o >>= 1) m = fmaxf(m, __shfl_xor_sync(0xffffffffu, m, o));
    if ((tid & 31) == 0) red[tid >> 5] = m;
    __syncthreads();
    m = red[0];
    #pragma unroll
    for (int w = 1; w < 8; w++) m = fmaxf(m, red[w]);
    float e0 = expf(scale * (f0.x - m));
    float e1 = expf(scale * (f0.y - m));
    float e2 = expf(scale * (f1.x - m));
    float e3 = expf(scale * (f1.y - m));
    float s = e0 + e1 + e2 + e3;
    #pragma unroll
    for (int o = 16; o > 0; o >>= 1) s += __shfl_xor_sync(0xffffffffu, s, o);
    __syncthreads();
    if ((tid & 31) == 0) red[tid >> 5] = s;
    __syncthreads();
    s = 0.0f;
    #pragma unroll
    for (int w = 0; w < 8; w++) s += red[w];
    float inv = 1.0f / s;
    row[2 * tid]     = __floats2half2_rn(e0 * inv, e1 * inv);
    row[2 * tid + 1] = __floats2half2_rn(e2 * inv, e3 * inv);
}

// reduce 3 K-split partials of f: f = (p0+p1+p2)/S + bvec; store x1024 fp16, col-permuted
__global__ void reduce_f_k() {
    long i = (long)blockIdx.x * 256 + threadIdx.x;    // 12288 x 256 = exactly B*S*E
    int c = (int)(i % E_DIM);
    long r = i / E_DIM;            // global row 0..4095
    int b = (int)(r >> 10);
    long rr = r & 1023;
    long base = rr * E_DIM + c;
    float s = g_fpart[(long)(0 * 4 + b) * SE_L + base]
            + g_fpart[(long)(1 * 4 + b) * SE_L + base]
            + g_fpart[(long)(2 * 4 + b) * SE_L + base];
    float val = s * (1.0f / (float)S_DIM) + g_bvec[b * E_DIM + c];
    int sc = (c & ~31) + STAB(c & 31);
    g_f[r * E_DIM + sc] = __float2half(val * 1024.0f);
}

// reduce 2 K-split partials of FF2: f2 = p0+p1 (already x1024 net); fp16, col-permuted
__global__ void reduce_ff2_k() {
    long i = (long)blockIdx.x * 256 + threadIdx.x;    // 12288 x 256
    int c = (int)(i % E_DIM);
    long r = i / E_DIM;
    const long TOT = (long)B_DIM * S_DIM * E_DIM;
    float val = g_f2part[i] + g_f2part[TOT + i];
    int sc = (c & ~31) + STAB(c & 31);
    g_f2[r * E_DIM + sc] = __float2half(val);
}

// ------------------------- fp16 cp.async NT GEMM (BN=128, R14 core) ---------------
// C[m,n] = ((alpha * sum_k A[m,k]*B[n,k]) + bias[n]) [GELU] * storeScale
// Operands fp16, K-permuted in gmem. Tile 128x128x64(halfs).
// 512 threads, 16 warps (4x4), warp tile 32x32, mma.m16n8k16.
// Batching: A = Ag + (z/divA)*sA; B = Bg + (z%modB)*sB + (z/divB)*sBz;
//           C = Cg + (z/divA)*sC1 + (z%modB)*sC2.
// smem row = 64 halfs (128B) = 8 chunks; logical chunk c at c ^ ((row&1)*4).
// Single __syncthreads per K-tile (arrival + stage-reuse, distance 3).

#define NS 4
#define STAGE_HALFS 16384           // 32KB: A 128x64 | B 128x64
#define GEMMH_SMEM (NS * STAGE_HALFS * 2)

template<bool GELU, bool PERM, typename OutT>
__global__ __launch_bounds__(512, 1)
void gemm_h(const __half* __restrict__ Ag, const __half* __restrict__ Bg,
            OutT* __restrict__ Cg,
            int M, int N, int K, int lda, int ldb, int ldc,
            long sA, long sB, long sC1, long sC2, int divA, int modB,
            long sBz, int divB,
            const float* __restrict__ alphaPtr, int alphaMod, float alphaScale,
            const float* __restrict__ biasPtr, long biasStride, float storeScale)
{
    extern __shared__ __half smh[];

    int z = blockIdx.z;
    const __half* A = Ag + (long)(z / divA) * sA;
    const __half* B = Bg + (long)(z % modB) * sB + (long)(z / divB) * sBz;
    OutT* C = Cg + (long)(z / divA) * sC1 + (long)(z % modB) * sC2;
    float alpha = alphaScale;
    if (alphaPtr) alpha *= alphaPtr[(z / divA) % alphaMod];
    const float* bias = biasPtr ? (biasPtr + (long)z * biasStride) : nullptr;

    int bm = blockIdx.x * 128;
    int bn = blockIdx.y * 128;
    int tid = threadIdx.x;
    int warp = tid >> 5, lane = tid & 31;
    int wm = warp >> 2, wn = warp & 3;     // 4x4 warp grid
    int g = lane >> 2, t = lane & 3;
    int gx = (g & 1) << 2;                 // row-parity XOR for this thread's rows/cols

    // producer: row = tid>>2 (0..127), logical chunks lc and lc+4
    int lrow = tid >> 2;
    int lc = tid & 3;
    int rpx = (lrow & 1) << 2;
    int am = bm + lrow;
    bool aok = am < M;
    const __half* abase = aok ? (A + (long)am * lda) : A;
    int nn = bn + lrow;
    bool bok = nn < N;
    const __half* bbase = bok ? (B + (long)nn * ldb) : B;
    int asz = aok ? 16 : 0, bsz = bok ? 16 : 0;

    uint32_t smb = s2u(smh);
    uint32_t dA0 = smb + (uint32_t)(lrow * 128 + ((lc      ^ rpx) << 4));
    uint32_t dA1 = smb + (uint32_t)(lrow * 128 + (((lc + 4) ^ rpx) << 4));
    uint32_t dB0 = dA0 + STAGE_HALFS;      // bytes offset: A half is 16384 B
    uint32_t dB1 = dA1 + STAGE_HALFS;

    float acc[2][4][4];
    #pragma unroll
    for (int i = 0; i < 2; i++)
        #pragma unroll
        for (int j = 0; j < 4; j++)
            #pragma unroll
            for (int r = 0; r < 4; r++) acc[i][j][r] = 0.0f;

    int nt = K >> 6;     // K multiple of 64

    #pragma unroll
    for (int p = 0; p < NS - 1; p++) {
        uint32_t off = p * (STAGE_HALFS * 2);
        int k0 = p * 64;
        cpa16(dA0 + off, abase + k0 + lc * 8,        asz);
        cpa16(dA1 + off, abase + k0 + (lc + 4) * 8,  asz);
        cpa16(dB0 + off, bbase + k0 + lc * 8,        bsz);
        cpa16(dB1 + off, bbase + k0 + (lc + 4) * 8,  bsz);
        CP_COMMIT();
    }

    for (int it = 0; it < nt; it++) {
        int s = it & (NS - 1);
        CP_WAIT(NS - 2);
        __syncthreads();     // single barrier: arrival + stage-reuse ordering

        int T = it + NS - 1;
        if (T < nt) {
            uint32_t off = (T & (NS - 1)) * (STAGE_HALFS * 2);
            int k0 = T << 6;
            cpa16(dA0 + off, abase + k0 + lc * 8,        asz);
            cpa16(dA1 + off, abase + k0 + (lc + 4) * 8,  asz);
            cpa16(dB0 + off, bbase + k0 + lc * 8,        bsz);
            cpa16(dB1 + off, bbase + k0 + (lc + 4) * 8,  bsz);
        }
        CP_COMMIT();

        const __half* As = smh + s * STAGE_HALFS;
        const __half* Bs = As + 8192;

        #pragma unroll
        for (int h = 0; h < 2; h++) {
            int cx = (t + 4 * h) ^ gx;     // stored chunk index for this thread
            F4 a[2][2], b[4];
            #pragma unroll
            for (int i = 0; i < 2; i++) {
                int r0 = wm * 32 + i * 16 + g;
                a[i][0].v = *reinterpret_cast<const float4*>(As + r0 * 64 + cx * 8);
                a[i][1].v = *reinterpret_cast<const float4*>(As + (r0 + 8) * 64 + cx * 8);
            }
            #pragma unroll
            for (int j = 0; j < 4; j++) {
                int cb = wn * 32 + j * 8 + g;
                b[j].v = *reinterpret_cast<const float4*>(Bs + cb * 64 + cx * 8);
            }
            #pragma unroll
            for (int i = 0; i < 2; i++)
                #pragma unroll
                for (int j = 0; j < 4; j++) {
                    mma16(acc[i][j], a[i][0].u[0], a[i][1].u[0], a[i][0].u[1], a[i][1].u[1],
                          b[j].u[0], b[j].u[1]);
                    mma16(acc[i][j], a[i][0].u[2], a[i][1].u[2], a[i][0].u[3], a[i][1].u[3],
                          b[j].u[2], b[j].u[3]);
                }
        }
    }

    // ---- epilogue ----
    #pragma unroll
    for (int i = 0; i < 2; i++) {
        #pragma unroll
        for (int j = 0; j < 4; j++) {
            int nl = wn * 32 + j * 8 + 2 * t;               // logical col in tile
            int n0 = bn + nl;
            int sn = PERM ? (bn + (nl & ~31) + STAB(nl & 31)) : n0;
            #pragma unroll
            for (int half = 0; half < 2; half++) {
                int m = bm + wm * 32 + i * 16 + g + half * 8;
                if (m >= M) continue;
                float v0 = acc[i][j][half * 2 + 0] * alpha;
                float v1 = acc[i][j][half * 2 + 1] * alpha;
                if (bias) { if (n0 < N) v0 += bias[n0]; if (n0 + 1 < N) v1 += bias[n0 + 1]; }
                if (GELU) {
                    v0 = 0.5f * v0 * (1.0f + erff(v0 * 0.70710678118654752f));
                    v1 = 0.5f * v1 * (1.0f + erff(v1 * 0.70710678118654752f));
                }
                v0 *= storeScale; v1 *= storeScale;
                OutT* crow = C + (long)m * ldc;
                if (n0 < N)     stv(crow + sn,     v0);
                if (n0 + 1 < N) stv(crow + sn + 1, v1);
            }
        }
    }
}

// ------------------------- launch -------------------------
extern "C" void kernel_launch(void* const* d_in, const int* in_sizes, int n_in,
                              void* d_out, int out_size) {
    (void)in_sizes; (void)n_in; (void)out_size;
    const int*   x     = (const int*)  d_in[0];
    const float* W_e   = (const float*)d_in[1];
    const float* W_p   = (const float*)d_in[2];
    const float* W_q   = (const float*)d_in[3];
    const float* W_k   = (const float*)d_in[4];
    const float* W_v   = (const float*)d_in[5];
    const float* A_lr  = (const float*)d_in[6];
    const float* B_lr  = (const float*)d_in[7];
    const float* ff_w1 = (const float*)d_in[8];
    const float* ff_w2 = (const float*)d_in[9];
    float* out = (float*)d_out;

    float *p_bvec, *p_fpart, *p_f2part;
    __half *p_v, *p_WeH, *p_WpH, *p_w1H, *p_w2H;
    __half *p_WqkT, *p_WvT, *p_QK, *p_attnT, *p_VtT, *p_f, *p_h1, *p_f2;
    cudaGetSymbolAddress((void**)&p_bvec,   g_bvec);
    cudaGetSymbolAddress((void**)&p_fpart,  g_fpart);
    cudaGetSymbolAddress((void**)&p_f2part, g_f2part);
    cudaGetSymbolAddress((void**)&p_v,      g_v);
    cudaGetSymbolAddress((void**)&p_WeH,    g_WeH);
    cudaGetSymbolAddress((void**)&p_WpH,    g_WpH);
    cudaGetSymbolAddress((void**)&p_w1H,    g_w1H);
    cudaGetSymbolAddress((void**)&p_w2H,    g_w2H);
    cudaGetSymbolAddress((void**)&p_WqkT,   g_WqkT);
    cudaGetSymbolAddress((void**)&p_WvT,    g_WvT);
    cudaGetSymbolAddress((void**)&p_QK,     g_QK);
    cudaGetSymbolAddress((void**)&p_attnT,  g_attnT);
    cudaGetSymbolAddress((void**)&p_VtT,    g_VtT);
    cudaGetSymbolAddress((void**)&p_f,      g_f);
    cudaGetSymbolAddress((void**)&p_h1,     g_h1);
    cudaGetSymbolAddress((void**)&p_f2,     g_f2);

    static bool attr_done = false;
    if (!attr_done) {
        cudaFuncSetAttribute(gemm_h<false, true,  __half>, cudaFuncAttributeMaxDynamicSharedMemorySize, GEMMH_SMEM);
        cudaFuncSetAttribute(gemm_h<true,  true,  __half>, cudaFuncAttributeMaxDynamicSharedMemorySize, GEMMH_SMEM);
        cudaFuncSetAttribute(gemm_h<false, false, float >, cudaFuncAttributeMaxDynamicSharedMemorySize, GEMMH_SMEM);
        attr_done = true;
    }

    const int BIG = 1 << 30;
    const long EE = (long)E_DIM * E_DIM;
    const long HS = (long)HS_DIM;
    const long SE = SE_L;
    const float SS = 1024.0f, ISS = 1.0f / 1024.0f;

    zero_init_k<<<1, 1024>>>();
    { dim3 g(3, 64); colmean_k<<<g, 256>>>(W_e); }
    { long nv = (long)B_DIM * S_DIM * E_DIM;
      embed_k<<<(int)((nv + 255) / 256), 256>>>(x, W_e); }
    { dim3 g(B_DIM, 16); bvec_k<<<g, E_DIM>>>(B_lr); }

    convert_perm_k<<<4096, 256>>>(W_e,   p_WeH, (long)V_DIM * E_DIM);
    convert_perm_k<<<1024, 256>>>(W_p,   p_WpH, SE);
    convert_perm_k<<<1024, 256>>>(ff_w1, p_w1H, (long)DFF_DIM * E_DIM);
    convert_perm_k<<<1024, 256>>>(ff_w2, p_w2H, (long)E_DIM * DFF_DIM);

    { dim3 g(24, 24, 12), b(32, 8);
      transpose_head_k<<<g, b>>>(W_q, p_WqkT);
      transpose_head_k<<<g, b>>>(W_k, p_WqkT + (long)H_DIM * EE);
      transpose_head_k<<<g, b>>>(W_v, p_WvT); }

    // QK merged: z=0..23 -> Q heads then K heads; one 1152-CTA launch
    { dim3 g(8, 6, 2 * H_DIM);
      gemm_h<false, true, __half><<<g, 512, GEMMH_SMEM>>>(p_WpH, p_WqkT, p_QK,
          S_DIM, E_DIM, E_DIM, E_DIM, E_DIM, E_DIM,
          0L, EE, SE, 0L, 1, BIG, 0L, 1,
          nullptr, 1, 1.0f, nullptr, 0L, 1.0f); }
    // attnT[q, h*S+s] = Q[h] @ K[h]^T
    { dim3 g(8, 8, H_DIM);
      gemm_h<false, true, __half><<<g, 512, GEMMH_SMEM>>>(p_QK, p_QK + (long)H_DIM * SE, p_attnT,
          S_DIM, S_DIM, E_DIM, E_DIM, E_DIM, HS_DIM,
          SE, SE, (long)S_DIM, 0L, 1, BIG, 0L, 1,
          nullptr, 1, 1.0f, nullptr, 0L, 1.0f); }
    softmax_h<<<S_DIM * H_DIM, 256>>>(p_attnT);

    // VtT[b][e][h*S+s] = A_lr[h] * (WvT[h] @ v[b]^T); z = h*B + b
    { dim3 g(6, 8, H_DIM * B_DIM);
      gemm_h<false, true, __half><<<g, 512, GEMMH_SMEM>>>(p_WvT, p_v, p_VtT,
          E_DIM, S_DIM, E_DIM, E_DIM, E_DIM, HS_DIM,
          EE, SE, (long)S_DIM, (long)E_DIM * HS, B_DIM, B_DIM, 0L, 1,
          A_lr, H_DIM, 1.0f, nullptr, 0L, 1.0f); }
    // f partials: K split 3x4096; z = ks*4 + b (576 CTAs)
    //   A = attnT + ks*4096; B = VtT + b*E*HS + ks*4096; C = fpart + z*SE (fp32, raw)
    { dim3 g(8, 6, 3 * B_DIM);
      gemm_h<false, false, float><<<g, 512, GEMMH_SMEM>>>(p_attnT, p_VtT, p_fpart,
          S_DIM, E_DIM, 4096, HS_DIM, HS_DIM, E_DIM,
          4096L, (long)E_DIM * HS, 4L * SE, SE, B_DIM, B_DIM, 4096L, B_DIM,
          nullptr, 1, 1.0f, nullptr, 0L, 1.0f); }
    reduce_f_k<<<12288, 256>>>();

    // h1 = gelu(f @ ff_w1^T); alpha undoes x1024; stored x1024
    { dim3 g(32, 24, 1);
      gemm_h<true, true, __half><<<g, 512, GEMMH_SMEM>>>(p_f, p_w1H, p_h1,
          B_DIM * S_DIM, DFF_DIM, E_DIM, E_DIM, E_DIM, DFF_DIM,
          0L, 0L, 0L, 0L, 1, BIG, 0L, 1,
          nullptr, 1, ISS, nullptr, 0L, SS); }
    // f2 partials: K split 2x1536; z = ks (384 CTAs); raw fp32
    { dim3 g(32, 6, 2);
      gemm_h<false, false, float><<<g, 512, GEMMH_SMEM>>>(p_h1, p_w2H, p_f2part,
          B_DIM * S_DIM, E_DIM, 1536, DFF_DIM, DFF_DIM, E_DIM,
          1536L, 1536L, (long)B_DIM * SE, 0L, 1, BIG, 0L, 1,
          nullptr, 1, 1.0f, nullptr, 0L, 1.0f); }
    reduce_ff2_k<<<12288, 256>>>();

    // logits: M=4096 (f2 batch-contiguous), N=50257; alpha undoes x1024
    { dim3 g(32, 393, 1);
      gemm_h<false, false, float><<<g, 512, GEMMH_SMEM>>>(p_f2, p_WeH, out,
          B_DIM * S_DIM, V_DIM, E_DIM, E_DIM, E_DIM, V_DIM,
          0L, 0L, 0L, 0L, 1, BIG, 0L, 1,
          nullptr, 1, ISS, nullptr, 0L, 1.0f); }
}